// round 13
// baseline (speedup 1.0000x reference)
#include <cuda_runtime.h>
#include <cuda_bf16.h>
#include <cstdint>

#define HGT 512
#define WID 512
#define NB 2
#define NCH 64
#define NPTS 131072
#define NMASK 131072
#define NBUCKET 2048

__device__ __align__(16) float g_mask[NB * HGT * WID];
__device__ int g_mode[2];
__device__ __align__(16) int g_hist[NBUCKET];
__device__ int g_perm[NPTS];

// ---------------------------------------------------------------------------
// Helpers
// ---------------------------------------------------------------------------
__device__ __forceinline__ uint32_t smem_u32(const void* p) {
    uint32_t a;
    asm("{ .reg .u64 t; cvta.to.shared.u64 t, %1; cvt.u32.u64 %0, t; }"
        : "=r"(a) : "l"(p));
    return a;
}
__device__ __forceinline__ uint32_t pack_bf(__nv_bfloat16 a, __nv_bfloat16 b) {
    __nv_bfloat162 t(a, b);
    return *reinterpret_cast<uint32_t*>(&t);
}
__device__ __forceinline__ void ldsm_x4(uint32_t* r, uint32_t addr) {
    asm volatile("ldmatrix.sync.aligned.m8n8.x4.shared.b16 {%0,%1,%2,%3}, [%4];"
                 : "=r"(r[0]), "=r"(r[1]), "=r"(r[2]), "=r"(r[3]) : "r"(addr));
}
__device__ __forceinline__ void ldsm_x4_t(uint32_t* r, uint32_t addr) {
    asm volatile("ldmatrix.sync.aligned.m8n8.x4.trans.shared.b16 {%0,%1,%2,%3}, [%4];"
                 : "=r"(r[0]), "=r"(r[1]), "=r"(r[2]), "=r"(r[3]) : "r"(addr));
}
__device__ __forceinline__ void mma_bf16(float* c, const uint32_t* a,
                                         uint32_t b0, uint32_t b1) {
    asm volatile(
        "mma.sync.aligned.m16n8k16.row.col.f32.bf16.bf16.f32 "
        "{%0,%1,%2,%3}, {%4,%5,%6,%7}, {%8,%9}, {%0,%1,%2,%3};"
        : "+f"(c[0]), "+f"(c[1]), "+f"(c[2]), "+f"(c[3])
        : "r"(a[0]), "r"(a[1]), "r"(a[2]), "r"(a[3]), "r"(b0), "r"(b1));
}
__device__ __forceinline__ unsigned long long pack64(float a, float b) {
    unsigned long long d;
    asm("mov.b64 %0, {%1, %2};" : "=l"(d) : "r"(__float_as_uint(a)), "r"(__float_as_uint(b)));
    return d;
}

// ---------------------------------------------------------------------------
// Index-format detection + robust row loader
// ---------------------------------------------------------------------------
__device__ __forceinline__ int detect_mode(const void* p) {
    const unsigned* w = (const unsigned*)p;
    bool hi_zero = true;
#pragma unroll
    for (int k = 0; k < 16; ++k) hi_zero &= (w[2 * k + 1] == 0u);
    if (hi_zero) return 0;
    bool small = true;
#pragma unroll
    for (int k = 0; k < 16; ++k) small &= (w[k] < 0x10000u);
    return small ? 1 : 2;
}

__global__ void detect_kernel(const void* idx, const void* midx) {
    if (threadIdx.x == 0) g_mode[0] = detect_mode(idx);
    if (threadIdx.x == 1) g_mode[1] = detect_mode(midx);
}

__device__ __forceinline__ void load_row3(const void* p, int i, int mode,
                                          int& b, int& y, int& x) {
    if (mode == 0) {
        const long long* q = (const long long*)p + 3 * (size_t)i;
        b = (int)q[0]; y = (int)q[1]; x = (int)q[2];
    } else if (mode == 1) {
        const int* q = (const int*)p + 3 * (size_t)i;
        b = q[0]; y = q[1]; x = q[2];
    } else {
        const float* q = (const float*)p + 3 * (size_t)i;
        b = (int)q[0]; y = (int)q[1]; x = (int)q[2];
    }
    b = b < 0 ? 0 : (b > NB - 1 ? NB - 1 : b);
    y = y < 0 ? 0 : (y > HGT - 1 ? HGT - 1 : y);
    x = x < 0 ? 0 : (x > WID - 1 ? WID - 1 : x);
}

__device__ __forceinline__ int bucket_key(int b, int y, int x) {
    return (b << 10) | ((y >> 4) << 5) | (x >> 4);
}

// ---------------------------------------------------------------------------
// Zero / mask scatter
// ---------------------------------------------------------------------------
__global__ void zero_kernel(float4* __restrict__ out4, int n_out4) {
    int i = blockIdx.x * blockDim.x + threadIdx.x;
    float4 z = make_float4(0.f, 0.f, 0.f, 0.f);
    if (i < n_out4) out4[i] = z;
    const int n_mask4 = NB * HGT * WID / 4;
    if (i < n_mask4) reinterpret_cast<float4*>(g_mask)[i] = z;
    if (i < NBUCKET / 4) reinterpret_cast<int4*>(g_hist)[i] = make_int4(0, 0, 0, 0);
}

__global__ void mask_scatter_kernel(const void* __restrict__ mi,
                                    const float* __restrict__ mv) {
    int i = blockIdx.x * blockDim.x + threadIdx.x;
    if (i < NMASK) {
        int b, y, x;
        load_row3(mi, i, g_mode[1], b, y, x);
        atomicAdd(&g_mask[(b * HGT + y) * WID + x], mv[i]);
    }
}

// ---------------------------------------------------------------------------
// Spatial counting sort: histogram -> scan -> place
// ---------------------------------------------------------------------------
__global__ void hist_kernel(const void* __restrict__ idx) {
    int i = blockIdx.x * blockDim.x + threadIdx.x;
    if (i < NPTS) {
        int b, y, x;
        load_row3(idx, i, g_mode[0], b, y, x);
        atomicAdd(&g_hist[bucket_key(b, y, x)], 1);
    }
}

__global__ void scan_kernel() {   // 1 block, 256 threads, 8 buckets each
    __shared__ int ws[256];
    const int t = threadIdx.x;
    int v[8];
    int local = 0;
#pragma unroll
    for (int j = 0; j < 8; ++j) {
        int tmp = g_hist[t * 8 + j];
        v[j] = local;
        local += tmp;
    }
    ws[t] = local;
    __syncthreads();
    for (int off = 1; off < 256; off <<= 1) {
        int add = (t >= off) ? ws[t - off] : 0;
        __syncthreads();
        ws[t] += add;
        __syncthreads();
    }
    int base = (t > 0) ? ws[t - 1] : 0;
#pragma unroll
    for (int j = 0; j < 8; ++j) g_hist[t * 8 + j] = base + v[j];
}

__global__ void place_kernel(const void* __restrict__ idx) {
    int i = blockIdx.x * blockDim.x + threadIdx.x;
    if (i < NPTS) {
        int b, y, x;
        load_row3(idx, i, g_mode[0], b, y, x);
        int pos = atomicAdd(&g_hist[bucket_key(b, y, x)], 1);
        g_perm[pos] = i;
    }
}

// ---------------------------------------------------------------------------
// Conv: warp-level mma.sync bf16 3-pass split GEMM + bfly-repacked red.v4
// scatter, over SPATIALLY SORTED points (g_perm) so concurrent scatters hit
// compact L2-resident regions.
// ---------------------------------------------------------------------------
#define SM_AHI 1536
#define SM_ALO 19968
#define SM_BHI 38400
#define SM_BLO 47616
#define SM_TOTAL 56832
#define PITCH 144

__global__ __launch_bounds__(256, 3)
void conv_mma_kernel(const float* __restrict__ values,
                     const float* __restrict__ kern,
                     const void* __restrict__ idx,
                     float* __restrict__ dense) {
    extern __shared__ char smem[];
    const uint32_t sb = smem_u32(smem);
    const int tid = threadIdx.x;
    const int wid = tid >> 5;
    const int lane = tid & 31;
    const int m0 = blockIdx.x * 128;

    int* Pb = reinterpret_cast<int*>(smem);
    int* Py = Pb + 128;
    int* Px = Py + 128;

    for (int i = tid; i < 128; i += 256) {
        int b, y, x;
        load_row3(idx, g_perm[m0 + i], g_mode[0], b, y, x);
        Pb[i] = b; Py[i] = y; Px[i] = x;
    }
    // Stage A hi/lo bf16 (once per block); rows gathered via perm (each row
    // is a contiguous 256B read -> coalesced across the 16 threads per row).
    {
        const float4* v4 = reinterpret_cast<const float4*>(values);
        for (int i = tid; i < 2048; i += 256) {
            int m = i >> 4, kc = (i & 15) << 2;
            float4 v = v4[(size_t)g_perm[m0 + m] * 16 + (i & 15)];
            __nv_bfloat16 h0 = __float2bfloat16(v.x), h1 = __float2bfloat16(v.y);
            __nv_bfloat16 h2 = __float2bfloat16(v.z), h3 = __float2bfloat16(v.w);
            __nv_bfloat16 l0 = __float2bfloat16(v.x - __bfloat162float(h0));
            __nv_bfloat16 l1 = __float2bfloat16(v.y - __bfloat162float(h1));
            __nv_bfloat16 l2 = __float2bfloat16(v.z - __bfloat162float(h2));
            __nv_bfloat16 l3 = __float2bfloat16(v.w - __bfloat162float(h3));
            uint32_t off = (uint32_t)(m * PITCH + kc * 2);
            *reinterpret_cast<uint32_t*>(smem + SM_AHI + off) = pack_bf(h0, h1);
            *reinterpret_cast<uint32_t*>(smem + SM_AHI + off + 4) = pack_bf(h2, h3);
            *reinterpret_cast<uint32_t*>(smem + SM_ALO + off) = pack_bf(l0, l1);
            *reinterpret_cast<uint32_t*>(smem + SM_ALO + off + 4) = pack_bf(l2, l3);
        }
    }

    const uint32_t a_base = sb + (uint32_t)((wid * 16 + (lane & 15)) * PITCH +
                                            ((lane >> 4) << 4));
    const uint32_t b_base = sb + (uint32_t)((lane & 15) * PITCH +
                                            ((lane >> 4) << 4));
    const int g = lane >> 2, tig = lane & 3;
    const int mA = wid * 16 + g;
    __syncthreads();
    const int pbA = Pb[mA], pyA = Py[mA], pxA = Px[mA];
    const int pbB = Pb[mA + 8], pyB = Py[mA + 8], pxB = Px[mA + 8];
    const int low = tig & 1;
    const int colbase = (tig & 2) * 2;

#pragma unroll 1
    for (int tap = 0; tap < 9; ++tap) {
        __syncthreads();
        {   // Stage B hi/lo: kern[tap] is [k][n] row-major.
            const float4* kt4 =
                reinterpret_cast<const float4*>(kern + (size_t)tap * NCH * NCH);
            for (int i = tid; i < 1024; i += 256) {
                int k = i >> 4, nc = (i & 15) << 2;
                float4 v = kt4[i];
                __nv_bfloat16 h0 = __float2bfloat16(v.x), h1 = __float2bfloat16(v.y);
                __nv_bfloat16 h2 = __float2bfloat16(v.z), h3 = __float2bfloat16(v.w);
                __nv_bfloat16 l0 = __float2bfloat16(v.x - __bfloat162float(h0));
                __nv_bfloat16 l1 = __float2bfloat16(v.y - __bfloat162float(h1));
                __nv_bfloat16 l2 = __float2bfloat16(v.z - __bfloat162float(h2));
                __nv_bfloat16 l3 = __float2bfloat16(v.w - __bfloat162float(h3));
                uint32_t off = (uint32_t)(k * PITCH + nc * 2);
                *reinterpret_cast<uint32_t*>(smem + SM_BHI + off) = pack_bf(h0, h1);
                *reinterpret_cast<uint32_t*>(smem + SM_BHI + off + 4) = pack_bf(h2, h3);
                *reinterpret_cast<uint32_t*>(smem + SM_BLO + off) = pack_bf(l0, l1);
                *reinterpret_cast<uint32_t*>(smem + SM_BLO + off + 4) = pack_bf(l2, l3);
            }
        }
        __syncthreads();

        float acc[8][4];
#pragma unroll
        for (int nt = 0; nt < 8; ++nt)
#pragma unroll
            for (int j = 0; j < 4; ++j) acc[nt][j] = 0.f;

#pragma unroll
        for (int pass = 0; pass < 3; ++pass) {
            const uint32_t abase = (pass < 2) ? (uint32_t)SM_AHI : (uint32_t)SM_ALO;
            const uint32_t bbase = (pass == 1) ? (uint32_t)SM_BLO : (uint32_t)SM_BHI;
#pragma unroll
            for (int ks = 0; ks < 4; ++ks) {
                uint32_t a[4];
                ldsm_x4(a, a_base + abase + ks * 32);
#pragma unroll
                for (int ntp = 0; ntp < 4; ++ntp) {
                    uint32_t b[4];
                    ldsm_x4_t(b, b_base + bbase + ks * (16 * PITCH) + ntp * 32);
                    mma_bf16(acc[2 * ntp], a, b[0], b[1]);
                    mma_bf16(acc[2 * ntp + 1], a, b[2], b[3]);
                }
            }
        }

        const int dy = tap / 3 - 1;
        const int dx = tap % 3 - 1;
        float* pA;
        {
            int sy = pyA + dy; sy = sy < 0 ? 0 : (sy > HGT - 1 ? HGT - 1 : sy);
            int sx = pxA + dx; sx = sx < 0 ? 0 : (sx > WID - 1 ? WID - 1 : sx);
            pA = dense + (((size_t)pbA * HGT + sy) * WID + sx) * NCH;
        }
        float* pB;
        {
            int sy = pyB + dy; sy = sy < 0 ? 0 : (sy > HGT - 1 ? HGT - 1 : sy);
            int sx = pxB + dx; sx = sx < 0 ? 0 : (sx > WID - 1 ? WID - 1 : sx);
            pB = dense + (((size_t)pbB * HGT + sy) * WID + sx) * NCH;
        }
#pragma unroll
        for (int h = 0; h < 2; ++h) {
            float* p = h ? pB : pA;
            const int i0 = 2 * h;
#pragma unroll
            for (int j = 0; j < 4; ++j) {
                unsigned long long snd =
                    low ? pack64(acc[2 * j][i0], acc[2 * j][i0 + 1])
                        : pack64(acc[2 * j + 1][i0], acc[2 * j + 1][i0 + 1]);
                unsigned long long rcv = __shfl_xor_sync(0xFFFFFFFFu, snd, 1);
                float r0 = __uint_as_float((unsigned int)rcv);
                float r1 = __uint_as_float((unsigned int)(rcv >> 32));
                int ntk = 2 * j + low;
                float f0, f1, f2, f3;
                if (low) { f0 = r0; f1 = r1; f2 = acc[ntk][i0]; f3 = acc[ntk][i0 + 1]; }
                else     { f0 = acc[ntk][i0]; f1 = acc[ntk][i0 + 1]; f2 = r0; f3 = r1; }
                asm volatile("red.global.add.v4.f32 [%0], {%1, %2, %3, %4};"
                             :: "l"(p + ntk * 8 + colbase),
                                "f"(f0), "f"(f1), "f"(f2), "f"(f3) : "memory");
            }
        }
    }
}

// ---------------------------------------------------------------------------
// Epilogue  out = (dense + mask*bias) * mask
// ---------------------------------------------------------------------------
__global__ void epilogue_kernel(float4* __restrict__ out4,
                                const float4* __restrict__ bias4) {
    int i = blockIdx.x * blockDim.x + threadIdx.x;
    float m = g_mask[i >> 4];
    float4 d = out4[i];
    float4 bv = __ldg(&bias4[i & 15]);
    d.x = (d.x + m * bv.x) * m;
    d.y = (d.y + m * bv.y) * m;
    d.z = (d.z + m * bv.z) * m;
    d.w = (d.w + m * bv.w) * m;
    out4[i] = d;
}

// ---------------------------------------------------------------------------
extern "C" void kernel_launch(void* const* d_in, const int* in_sizes, int n_in,
                              void* d_out, int out_size) {
    const float* values = nullptr;
    const float* kern = nullptr;
    const float* bias = nullptr;
    const float* mask_values = nullptr;
    const void* indices = nullptr;
    const void* mask_indices = nullptr;

    for (int i = 0; i < n_in; ++i) {
        int s = in_sizes[i];
        if (s == 8388608)      values = (const float*)d_in[i];
        else if (s == 36864)   kern = (const float*)d_in[i];
        else if (s == 64)      bias = (const float*)d_in[i];
        else if (s == 131072)  mask_values = (const float*)d_in[i];
        else if (s == 393216 || s == 786432) {
            if (!indices) indices = d_in[i];
            else          mask_indices = d_in[i];
        }
    }
    if (!values)       values       = (const float*)d_in[0];
    if (!kern)         kern         = (const float*)d_in[1];
    if (!bias)         bias         = (const float*)d_in[2];
    if (!mask_values)  mask_values  = (const float*)d_in[3];
    if (!indices)      indices      = d_in[4];
    if (!mask_indices) mask_indices = d_in[5];

    float* out = (float*)d_out;
    const int n_out4 = NB * HGT * WID * NCH / 4;  // 8388608

    static bool attr_set = false;
    if (!attr_set) {
        cudaFuncSetAttribute(conv_mma_kernel,
                             cudaFuncAttributeMaxDynamicSharedMemorySize, SM_TOTAL);
        attr_set = true;
    }

    detect_kernel<<<1, 32>>>(indices, mask_indices);
    zero_kernel<<<(n_out4 + 255) / 256, 256>>>((float4*)out, n_out4);
    mask_scatter_kernel<<<(NMASK + 255) / 256, 256>>>(mask_indices, mask_values);
    hist_kernel<<<NPTS / 256, 256>>>(indices);
    scan_kernel<<<1, 256>>>();
    place_kernel<<<NPTS / 256, 256>>>(indices);
    conv_mma_kernel<<<NPTS / 128, 256, SM_TOTAL>>>(values, kern, indices, out);
    epilogue_kernel<<<n_out4 / 256, 256>>>((float4*)out, (const float4*)bias);
}

// round 14
// speedup vs baseline: 1.8511x; 1.8511x over previous
#include <cuda_runtime.h>
#include <cstdint>

#define HGT 512
#define WID 512
#define NB 2
#define NCH 64
#define NPTS 131072
#define NMASK 131072

// Scratch via __device__ globals (allocations are forbidden).
__device__ __align__(16) float g_mask[NB * HGT * WID];
__device__ int g_mode[2];   // 0 = int64 rows, 1 = int32 rows, 2 = float32 rows

// ---------------------------------------------------------------------------
// Index-format detection + robust row loader
// ---------------------------------------------------------------------------
__device__ __forceinline__ int detect_mode(const void* p) {
    const unsigned* w = (const unsigned*)p;
    bool hi_zero = true;
#pragma unroll
    for (int k = 0; k < 16; ++k) hi_zero &= (w[2 * k + 1] == 0u);
    if (hi_zero) return 0;
    bool small = true;
#pragma unroll
    for (int k = 0; k < 16; ++k) small &= (w[k] < 0x10000u);
    return small ? 1 : 2;
}

__device__ __forceinline__ void load_row3(const void* p, int i, int mode,
                                          int& b, int& y, int& x) {
    if (mode == 0) {
        const long long* q = (const long long*)p + 3 * (size_t)i;
        b = (int)q[0]; y = (int)q[1]; x = (int)q[2];
    } else if (mode == 1) {
        const int* q = (const int*)p + 3 * (size_t)i;
        b = q[0]; y = q[1]; x = q[2];
    } else {
        const float* q = (const float*)p + 3 * (size_t)i;
        b = (int)q[0]; y = (int)q[1]; x = (int)q[2];
    }
    b = b < 0 ? 0 : (b > NB - 1 ? NB - 1 : b);
    y = y < 0 ? 0 : (y > HGT - 1 ? HGT - 1 : y);
    x = x < 0 ? 0 : (x > WID - 1 ? WID - 1 : x);
}

// ---------------------------------------------------------------------------
// Packed f32x2 helpers (sm_103a 2x fp32 path)
// ---------------------------------------------------------------------------
__device__ __forceinline__ unsigned long long fma2(unsigned long long a,
                                                   unsigned long long b,
                                                   unsigned long long c) {
    unsigned long long d;
    asm("fma.rn.f32x2 %0, %1, %2, %3;" : "=l"(d) : "l"(a), "l"(b), "l"(c));
    return d;
}
__device__ __forceinline__ unsigned long long splat2(float a) {
    unsigned long long d;
    unsigned int ai = __float_as_uint(a);
    asm("mov.b64 %0, {%1, %2};" : "=l"(d) : "r"(ai), "r"(ai));
    return d;
}

// ---------------------------------------------------------------------------
// Kernel 1: zero the dense accumulator (d_out) + mask grid, and detect the
// index dtype (folded in to save a launch).
// ---------------------------------------------------------------------------
__global__ void zero_kernel(float4* __restrict__ out4, int n_out4,
                            const void* __restrict__ idx,
                            const void* __restrict__ midx) {
    int i = blockIdx.x * blockDim.x + threadIdx.x;
    if (i == 0) g_mode[0] = detect_mode(idx);
    if (i == 1) g_mode[1] = detect_mode(midx);
    float4 z = make_float4(0.f, 0.f, 0.f, 0.f);
    if (i < n_out4) out4[i] = z;
    const int n_mask4 = NB * HGT * WID / 4;
    if (i < n_mask4) reinterpret_cast<float4*>(g_mask)[i] = z;
}

// ---------------------------------------------------------------------------
// Kernel 2: scatter mask_values into the mask grid.
// ---------------------------------------------------------------------------
__global__ void mask_scatter_kernel(const void* __restrict__ mi,
                                    const float* __restrict__ mv) {
    int i = blockIdx.x * blockDim.x + threadIdx.x;
    if (i < NMASK) {
        int b, y, x;
        load_row3(mi, i, g_mode[1], b, y, x);
        atomicAdd(&g_mask[(b * HGT + y) * WID + x], mv[i]);
    }
}

// ---------------------------------------------------------------------------
// Kernel 3: fused per-tap GEMM (128 points x 64 out, K=64) + vector-red
// scatter. 256 threads = 16x16; thread (ty,tx) owns 8 m-rows x 4 channels.
// Proven R8 shape: m-pair packed A (k-major smem), 4 B splats, 16 FFMA2/k,
// 4 CTAs/SM (reg cap 64). Mainloop unroll widened 8 -> 16 for deeper LDS
// batching against the FFMA2 stream.
// ---------------------------------------------------------------------------
__global__ __launch_bounds__(256, 4) void conv_scatter_kernel(
    const float* __restrict__ values, const float* __restrict__ kern,
    const void* __restrict__ idx, float* __restrict__ dense) {
    __shared__ float As[64][132];   // k-major values tile (+4 pad), ~33 KB
    __shared__ float Bs[64][64];    // one tap's 64x64 kernel slice, 16 KB
    __shared__ int Pb[128], Py[128], Px[128];

    const int tid = threadIdx.x;
    const int m0 = blockIdx.x * 128;
    const int mode = g_mode[0];

    // Point coords first so their LDGs overlap the A staging below.
    for (int i = tid; i < 128; i += 256) {
        int b, y, x;
        load_row3(idx, m0 + i, mode, b, y, x);
        Pb[i] = b; Py[i] = y; Px[i] = x;
    }
    // Stage A transposed: coalesced float4 gmem reads, scalar smem stores.
    for (int i = tid; i < 128 * 16; i += 256) {
        int m = i >> 4;
        int c = (i & 15) << 2;
        float4 v = *reinterpret_cast<const float4*>(values + (size_t)(m0 + m) * NCH + c);
        As[c + 0][m] = v.x;
        As[c + 1][m] = v.y;
        As[c + 2][m] = v.z;
        As[c + 3][m] = v.w;
    }

    const int ty = tid >> 4;   // 0..15 -> 8 consecutive m-rows each
    const int tx = tid & 15;   // 0..15 -> 4 channels each

#pragma unroll 1
    for (int tap = 0; tap < 9; ++tap) {
        __syncthreads();
        const float4* bsrc = reinterpret_cast<const float4*>(kern + (size_t)tap * NCH * NCH);
        for (int i = tid; i < 64 * 16; i += 256)
            reinterpret_cast<float4*>(Bs)[i] = bsrc[i];
        __syncthreads();

        unsigned long long acc[4][4];   // [m-pair][channel]
#pragma unroll
        for (int mp = 0; mp < 4; ++mp)
#pragma unroll
            for (int n = 0; n < 4; ++n) acc[mp][n] = 0ull;

#pragma unroll 16
        for (int k = 0; k < 64; ++k) {
            // A: 8 consecutive m values as 4 pre-packed f32x2 pairs.
            ulonglong2 A0 = *reinterpret_cast<const ulonglong2*>(&As[k][ty * 8]);
            ulonglong2 A1 = *reinterpret_cast<const ulonglong2*>(&As[k][ty * 8 + 4]);
            // B: one LDS.128, then 4 channel splats.
            float4 b = *reinterpret_cast<const float4*>(&Bs[k][tx * 4]);
            unsigned long long sb0 = splat2(b.x), sb1 = splat2(b.y);
            unsigned long long sb2 = splat2(b.z), sb3 = splat2(b.w);
            acc[0][0] = fma2(A0.x, sb0, acc[0][0]);
            acc[0][1] = fma2(A0.x, sb1, acc[0][1]);
            acc[0][2] = fma2(A0.x, sb2, acc[0][2]);
            acc[0][3] = fma2(A0.x, sb3, acc[0][3]);
            acc[1][0] = fma2(A0.y, sb0, acc[1][0]);
            acc[1][1] = fma2(A0.y, sb1, acc[1][1]);
            acc[1][2] = fma2(A0.y, sb2, acc[1][2]);
            acc[1][3] = fma2(A0.y, sb3, acc[1][3]);
            acc[2][0] = fma2(A1.x, sb0, acc[2][0]);
            acc[2][1] = fma2(A1.x, sb1, acc[2][1]);
            acc[2][2] = fma2(A1.x, sb2, acc[2][2]);
            acc[2][3] = fma2(A1.x, sb3, acc[2][3]);
            acc[3][0] = fma2(A1.y, sb0, acc[3][0]);
            acc[3][1] = fma2(A1.y, sb1, acc[3][1]);
            acc[3][2] = fma2(A1.y, sb2, acc[3][2]);
            acc[3][3] = fma2(A1.y, sb3, acc[3][3]);
        }

        const int dy = tap / 3 - 1;
        const int dx = tap % 3 - 1;
#pragma unroll
        for (int mp = 0; mp < 4; ++mp) {
#pragma unroll
            for (int e = 0; e < 2; ++e) {
                int m = ty * 8 + mp * 2 + e;
                int sy = Py[m] + dy;
                sy = sy < 0 ? 0 : (sy > HGT - 1 ? HGT - 1 : sy);
                int sx = Px[m] + dx;
                sx = sx < 0 ? 0 : (sx > WID - 1 ? WID - 1 : sx);
                float* p = dense + ((((size_t)Pb[m] * HGT + sy) * WID + sx) * NCH) + tx * 4;
                float f0, f1, f2, f3;
                if (e == 0) {
                    f0 = __uint_as_float((unsigned int)acc[mp][0]);
                    f1 = __uint_as_float((unsigned int)acc[mp][1]);
                    f2 = __uint_as_float((unsigned int)acc[mp][2]);
                    f3 = __uint_as_float((unsigned int)acc[mp][3]);
                } else {
                    f0 = __uint_as_float((unsigned int)(acc[mp][0] >> 32));
                    f1 = __uint_as_float((unsigned int)(acc[mp][1] >> 32));
                    f2 = __uint_as_float((unsigned int)(acc[mp][2] >> 32));
                    f3 = __uint_as_float((unsigned int)(acc[mp][3] >> 32));
                }
                asm volatile("red.global.add.v4.f32 [%0], {%1, %2, %3, %4};"
                             :: "l"(p), "f"(f0), "f"(f1), "f"(f2), "f"(f3)
                             : "memory");
            }
        }
    }
}

// ---------------------------------------------------------------------------
// Kernel 4: epilogue  out = (dense + mask*bias) * mask   (in place on d_out)
// ---------------------------------------------------------------------------
__global__ void epilogue_kernel(float4* __restrict__ out4,
                                const float4* __restrict__ bias4) {
    int i = blockIdx.x * blockDim.x + threadIdx.x;
    float m = g_mask[i >> 4];
    float4 d = out4[i];
    float4 bv = __ldg(&bias4[i & 15]);
    d.x = (d.x + m * bv.x) * m;
    d.y = (d.y + m * bv.y) * m;
    d.z = (d.z + m * bv.z) * m;
    d.w = (d.w + m * bv.w) * m;
    out4[i] = d;
}

// ---------------------------------------------------------------------------
extern "C" void kernel_launch(void* const* d_in, const int* in_sizes, int n_in,
                              void* d_out, int out_size) {
    const float* values = nullptr;
    const float* kern = nullptr;
    const float* bias = nullptr;
    const float* mask_values = nullptr;
    const void* indices = nullptr;
    const void* mask_indices = nullptr;

    for (int i = 0; i < n_in; ++i) {
        int s = in_sizes[i];
        if (s == 8388608)      values = (const float*)d_in[i];
        else if (s == 36864)   kern = (const float*)d_in[i];
        else if (s == 64)      bias = (const float*)d_in[i];
        else if (s == 131072)  mask_values = (const float*)d_in[i];
        else if (s == 393216 || s == 786432) {
            if (!indices) indices = d_in[i];
            else          mask_indices = d_in[i];
        }
    }
    if (!values)       values       = (const float*)d_in[0];
    if (!kern)         kern         = (const float*)d_in[1];
    if (!bias)         bias         = (const float*)d_in[2];
    if (!mask_values)  mask_values  = (const float*)d_in[3];
    if (!indices)      indices      = d_in[4];
    if (!mask_indices) mask_indices = d_in[5];

    float* out = (float*)d_out;
    const int n_out4 = NB * HGT * WID * NCH / 4;  // 8388608

    zero_kernel<<<(n_out4 + 255) / 256, 256>>>((float4*)out, n_out4,
                                               indices, mask_indices);
    mask_scatter_kernel<<<(NMASK + 255) / 256, 256>>>(mask_indices, mask_values);
    conv_scatter_kernel<<<NPTS / 128, 256>>>(values, kern, indices, out);
    epilogue_kernel<<<n_out4 / 256, 256>>>((float4*)out, (const float4*)bias);
}

// round 15
// speedup vs baseline: 1.9119x; 1.0329x over previous
#include <cuda_runtime.h>
#include <cstdint>

#define HGT 512
#define WID 512
#define NB 2
#define NCH 64
#define NPTS 131072
#define NMASK 131072

// Scratch via __device__ globals (allocations are forbidden).
__device__ __align__(16) float g_mask[NB * HGT * WID];
__device__ int g_mode[2];   // 0 = int64 rows, 1 = int32 rows, 2 = float32 rows

// ---------------------------------------------------------------------------
// Index-format detection + robust row loader
// ---------------------------------------------------------------------------
__device__ __forceinline__ int detect_mode(const void* p) {
    const unsigned* w = (const unsigned*)p;
    bool hi_zero = true;
#pragma unroll
    for (int k = 0; k < 16; ++k) hi_zero &= (w[2 * k + 1] == 0u);
    if (hi_zero) return 0;
    bool small = true;
#pragma unroll
    for (int k = 0; k < 16; ++k) small &= (w[k] < 0x10000u);
    return small ? 1 : 2;
}

__device__ __forceinline__ void load_row3(const void* p, int i, int mode,
                                          int& b, int& y, int& x) {
    if (mode == 0) {
        const long long* q = (const long long*)p + 3 * (size_t)i;
        b = (int)q[0]; y = (int)q[1]; x = (int)q[2];
    } else if (mode == 1) {
        const int* q = (const int*)p + 3 * (size_t)i;
        b = q[0]; y = q[1]; x = q[2];
    } else {
        const float* q = (const float*)p + 3 * (size_t)i;
        b = (int)q[0]; y = (int)q[1]; x = (int)q[2];
    }
    b = b < 0 ? 0 : (b > NB - 1 ? NB - 1 : b);
    y = y < 0 ? 0 : (y > HGT - 1 ? HGT - 1 : y);
    x = x < 0 ? 0 : (x > WID - 1 ? WID - 1 : x);
}

// ---------------------------------------------------------------------------
// Packed f32x2 helpers (sm_103a 2x fp32 path)
// ---------------------------------------------------------------------------
__device__ __forceinline__ unsigned long long fma2(unsigned long long a,
                                                   unsigned long long b,
                                                   unsigned long long c) {
    unsigned long long d;
    asm("fma.rn.f32x2 %0, %1, %2, %3;" : "=l"(d) : "l"(a), "l"(b), "l"(c));
    return d;
}
__device__ __forceinline__ unsigned long long splat2(float a) {
    unsigned long long d;
    unsigned int ai = __float_as_uint(a);
    asm("mov.b64 %0, {%1, %2};" : "=l"(d) : "r"(ai), "r"(ai));
    return d;
}

// ---------------------------------------------------------------------------
// Kernel 1: zero the dense accumulator (d_out) + mask grid, and detect the
// index dtype (folded in to save a launch).
// ---------------------------------------------------------------------------
__global__ void zero_kernel(float4* __restrict__ out4, int n_out4,
                            const void* __restrict__ idx,
                            const void* __restrict__ midx) {
    int i = blockIdx.x * blockDim.x + threadIdx.x;
    if (i == 0) g_mode[0] = detect_mode(idx);
    if (i == 1) g_mode[1] = detect_mode(midx);
    float4 z = make_float4(0.f, 0.f, 0.f, 0.f);
    if (i < n_out4) out4[i] = z;
    const int n_mask4 = NB * HGT * WID / 4;
    if (i < n_mask4) reinterpret_cast<float4*>(g_mask)[i] = z;
}

// ---------------------------------------------------------------------------
// Kernel 2: scatter mask_values into the mask grid.
// ---------------------------------------------------------------------------
__global__ void mask_scatter_kernel(const void* __restrict__ mi,
                                    const float* __restrict__ mv) {
    int i = blockIdx.x * blockDim.x + threadIdx.x;
    if (i < NMASK) {
        int b, y, x;
        load_row3(mi, i, g_mode[1], b, y, x);
        atomicAdd(&g_mask[(b * HGT + y) * WID + x], mv[i]);
    }
}

// ---------------------------------------------------------------------------
// Kernel 3: fused per-tap GEMM (128 points x 64 out, K=64) + vector-red
// scatter. 256 threads = 16x16; thread (ty,tx) owns 8 m-rows x 4 channels.
// Proven R8 shape: m-pair packed A (k-major smem), 4 B splats, 16 FFMA2/k,
// 4 CTAs/SM (reg cap 64), mainloop unroll 8.
// ---------------------------------------------------------------------------
__global__ __launch_bounds__(256, 4) void conv_scatter_kernel(
    const float* __restrict__ values, const float* __restrict__ kern,
    const void* __restrict__ idx, float* __restrict__ dense) {
    __shared__ float As[64][132];   // k-major values tile (+4 pad), ~33 KB
    __shared__ float Bs[64][64];    // one tap's 64x64 kernel slice, 16 KB
    __shared__ int Pb[128], Py[128], Px[128];

    const int tid = threadIdx.x;
    const int m0 = blockIdx.x * 128;
    const int mode = g_mode[0];

    // Point coords first so their LDGs overlap the A staging below.
    for (int i = tid; i < 128; i += 256) {
        int b, y, x;
        load_row3(idx, m0 + i, mode, b, y, x);
        Pb[i] = b; Py[i] = y; Px[i] = x;
    }
    // Stage A transposed: coalesced float4 gmem reads, scalar smem stores.
    for (int i = tid; i < 128 * 16; i += 256) {
        int m = i >> 4;
        int c = (i & 15) << 2;
        float4 v = *reinterpret_cast<const float4*>(values + (size_t)(m0 + m) * NCH + c);
        As[c + 0][m] = v.x;
        As[c + 1][m] = v.y;
        As[c + 2][m] = v.z;
        As[c + 3][m] = v.w;
    }

    const int ty = tid >> 4;   // 0..15 -> 8 consecutive m-rows each
    const int tx = tid & 15;   // 0..15 -> 4 channels each

#pragma unroll 1
    for (int tap = 0; tap < 9; ++tap) {
        __syncthreads();
        const float4* bsrc = reinterpret_cast<const float4*>(kern + (size_t)tap * NCH * NCH);
        for (int i = tid; i < 64 * 16; i += 256)
            reinterpret_cast<float4*>(Bs)[i] = bsrc[i];
        __syncthreads();

        unsigned long long acc[4][4];   // [m-pair][channel]
#pragma unroll
        for (int mp = 0; mp < 4; ++mp)
#pragma unroll
            for (int n = 0; n < 4; ++n) acc[mp][n] = 0ull;

#pragma unroll 8
        for (int k = 0; k < 64; ++k) {
            // A: 8 consecutive m values as 4 pre-packed f32x2 pairs.
            ulonglong2 A0 = *reinterpret_cast<const ulonglong2*>(&As[k][ty * 8]);
            ulonglong2 A1 = *reinterpret_cast<const ulonglong2*>(&As[k][ty * 8 + 4]);
            // B: one LDS.128, then 4 channel splats.
            float4 b = *reinterpret_cast<const float4*>(&Bs[k][tx * 4]);
            unsigned long long sb0 = splat2(b.x), sb1 = splat2(b.y);
            unsigned long long sb2 = splat2(b.z), sb3 = splat2(b.w);
            acc[0][0] = fma2(A0.x, sb0, acc[0][0]);
            acc[0][1] = fma2(A0.x, sb1, acc[0][1]);
            acc[0][2] = fma2(A0.x, sb2, acc[0][2]);
            acc[0][3] = fma2(A0.x, sb3, acc[0][3]);
            acc[1][0] = fma2(A0.y, sb0, acc[1][0]);
            acc[1][1] = fma2(A0.y, sb1, acc[1][1]);
            acc[1][2] = fma2(A0.y, sb2, acc[1][2]);
            acc[1][3] = fma2(A0.y, sb3, acc[1][3]);
            acc[2][0] = fma2(A1.x, sb0, acc[2][0]);
            acc[2][1] = fma2(A1.x, sb1, acc[2][1]);
            acc[2][2] = fma2(A1.x, sb2, acc[2][2]);
            acc[2][3] = fma2(A1.x, sb3, acc[2][3]);
            acc[3][0] = fma2(A1.y, sb0, acc[3][0]);
            acc[3][1] = fma2(A1.y, sb1, acc[3][1]);
            acc[3][2] = fma2(A1.y, sb2, acc[3][2]);
            acc[3][3] = fma2(A1.y, sb3, acc[3][3]);
        }

        const int dy = tap / 3 - 1;
        const int dx = tap % 3 - 1;
#pragma unroll
        for (int mp = 0; mp < 4; ++mp) {
#pragma unroll
            for (int e = 0; e < 2; ++e) {
                int m = ty * 8 + mp * 2 + e;
                int sy = Py[m] + dy;
                sy = sy < 0 ? 0 : (sy > HGT - 1 ? HGT - 1 : sy);
                int sx = Px[m] + dx;
                sx = sx < 0 ? 0 : (sx > WID - 1 ? WID - 1 : sx);
                float* p = dense + ((((size_t)Pb[m] * HGT + sy) * WID + sx) * NCH) + tx * 4;
                float f0, f1, f2, f3;
                if (e == 0) {
                    f0 = __uint_as_float((unsigned int)acc[mp][0]);
                    f1 = __uint_as_float((unsigned int)acc[mp][1]);
                    f2 = __uint_as_float((unsigned int)acc[mp][2]);
                    f3 = __uint_as_float((unsigned int)acc[mp][3]);
                } else {
                    f0 = __uint_as_float((unsigned int)(acc[mp][0] >> 32));
                    f1 = __uint_as_float((unsigned int)(acc[mp][1] >> 32));
                    f2 = __uint_as_float((unsigned int)(acc[mp][2] >> 32));
                    f3 = __uint_as_float((unsigned int)(acc[mp][3] >> 32));
                }
                asm volatile("red.global.add.v4.f32 [%0], {%1, %2, %3, %4};"
                             :: "l"(p), "f"(f0), "f"(f1), "f"(f2), "f"(f3)
                             : "memory");
            }
        }
    }
}

// ---------------------------------------------------------------------------
// Kernel 4: epilogue  out = (dense + mask*bias) * mask   (in place on d_out)
// mask==0 on ~78% of pixels -> skip the dense READ there and store zeros.
// One pixel = 16 consecutive float4; the branch is uniform per half-warp.
// ---------------------------------------------------------------------------
__global__ void epilogue_kernel(float4* __restrict__ out4,
                                const float4* __restrict__ bias4) {
    int i = blockIdx.x * blockDim.x + threadIdx.x;
    float m = g_mask[i >> 4];
    if (m == 0.f) {
        out4[i] = make_float4(0.f, 0.f, 0.f, 0.f);
        return;
    }
    float4 d = out4[i];
    float4 bv = __ldg(&bias4[i & 15]);
    d.x = (d.x + m * bv.x) * m;
    d.y = (d.y + m * bv.y) * m;
    d.z = (d.z + m * bv.z) * m;
    d.w = (d.w + m * bv.w) * m;
    out4[i] = d;
}

// ---------------------------------------------------------------------------
extern "C" void kernel_launch(void* const* d_in, const int* in_sizes, int n_in,
                              void* d_out, int out_size) {
    const float* values = nullptr;
    const float* kern = nullptr;
    const float* bias = nullptr;
    const float* mask_values = nullptr;
    const void* indices = nullptr;
    const void* mask_indices = nullptr;

    for (int i = 0; i < n_in; ++i) {
        int s = in_sizes[i];
        if (s == 8388608)      values = (const float*)d_in[i];
        else if (s == 36864)   kern = (const float*)d_in[i];
        else if (s == 64)      bias = (const float*)d_in[i];
        else if (s == 131072)  mask_values = (const float*)d_in[i];
        else if (s == 393216 || s == 786432) {
            if (!indices) indices = d_in[i];
            else          mask_indices = d_in[i];
        }
    }
    if (!values)       values       = (const float*)d_in[0];
    if (!kern)         kern         = (const float*)d_in[1];
    if (!bias)         bias         = (const float*)d_in[2];
    if (!mask_values)  mask_values  = (const float*)d_in[3];
    if (!indices)      indices      = d_in[4];
    if (!mask_indices) mask_indices = d_in[5];

    float* out = (float*)d_out;
    const int n_out4 = NB * HGT * WID * NCH / 4;  // 8388608

    zero_kernel<<<(n_out4 + 255) / 256, 256>>>((float4*)out, n_out4,
                                               indices, mask_indices);
    mask_scatter_kernel<<<(NMASK + 255) / 256, 256>>>(mask_indices, mask_values);
    conv_scatter_kernel<<<NPTS / 128, 256>>>(values, kern, indices, out);
    epilogue_kernel<<<n_out4 / 256, 256>>>((float4*)out, (const float4*)bias);
}

// round 16
// speedup vs baseline: 1.9266x; 1.0077x over previous
#include <cuda_runtime.h>
#include <cstdint>

#define HGT 512
#define WID 512
#define NB 2
#define NCH 64
#define NPTS 131072
#define NMASK 131072

// Scratch via __device__ globals (allocations are forbidden).
__device__ __align__(16) float g_mask[NB * HGT * WID];
__device__ int g_mode[2];   // 0 = int64 rows, 1 = int32 rows, 2 = float32 rows

// ---------------------------------------------------------------------------
// Index-format detection + robust row loader
// ---------------------------------------------------------------------------
__device__ __forceinline__ int detect_mode(const void* p) {
    const unsigned* w = (const unsigned*)p;
    bool hi_zero = true;
#pragma unroll
    for (int k = 0; k < 16; ++k) hi_zero &= (w[2 * k + 1] == 0u);
    if (hi_zero) return 0;
    bool small = true;
#pragma unroll
    for (int k = 0; k < 16; ++k) small &= (w[k] < 0x10000u);
    return small ? 1 : 2;
}

__device__ __forceinline__ void load_row3(const void* p, int i, int mode,
                                          int& b, int& y, int& x) {
    if (mode == 0) {
        const long long* q = (const long long*)p + 3 * (size_t)i;
        b = (int)q[0]; y = (int)q[1]; x = (int)q[2];
    } else if (mode == 1) {
        const int* q = (const int*)p + 3 * (size_t)i;
        b = q[0]; y = q[1]; x = q[2];
    } else {
        const float* q = (const float*)p + 3 * (size_t)i;
        b = (int)q[0]; y = (int)q[1]; x = (int)q[2];
    }
    b = b < 0 ? 0 : (b > NB - 1 ? NB - 1 : b);
    y = y < 0 ? 0 : (y > HGT - 1 ? HGT - 1 : y);
    x = x < 0 ? 0 : (x > WID - 1 ? WID - 1 : x);
}

// ---------------------------------------------------------------------------
// Packed f32x2 helpers (sm_103a 2x fp32 path)
// ---------------------------------------------------------------------------
__device__ __forceinline__ unsigned long long fma2(unsigned long long a,
                                                   unsigned long long b,
                                                   unsigned long long c) {
    unsigned long long d;
    asm("fma.rn.f32x2 %0, %1, %2, %3;" : "=l"(d) : "l"(a), "l"(b), "l"(c));
    return d;
}
__device__ __forceinline__ unsigned long long splat2(float a) {
    unsigned long long d;
    unsigned int ai = __float_as_uint(a);
    asm("mov.b64 %0, {%1, %2};" : "=l"(d) : "r"(ai), "r"(ai));
    return d;
}

// ---------------------------------------------------------------------------
// Kernel 1: zero the dense accumulator (d_out) + mask grid, and detect the
// index dtype (folded in to save a launch).
// ---------------------------------------------------------------------------
__global__ void zero_kernel(float4* __restrict__ out4, int n_out4,
                            const void* __restrict__ idx,
                            const void* __restrict__ midx) {
    int i = blockIdx.x * blockDim.x + threadIdx.x;
    if (i == 0) g_mode[0] = detect_mode(idx);
    if (i == 1) g_mode[1] = detect_mode(midx);
    float4 z = make_float4(0.f, 0.f, 0.f, 0.f);
    if (i < n_out4) out4[i] = z;
    const int n_mask4 = NB * HGT * WID / 4;
    if (i < n_mask4) reinterpret_cast<float4*>(g_mask)[i] = z;
}

// ---------------------------------------------------------------------------
// Kernel 2: scatter mask_values into the mask grid.
// ---------------------------------------------------------------------------
__global__ void mask_scatter_kernel(const void* __restrict__ mi,
                                    const float* __restrict__ mv) {
    int i = blockIdx.x * blockDim.x + threadIdx.x;
    if (i < NMASK) {
        int b, y, x;
        load_row3(mi, i, g_mode[1], b, y, x);
        atomicAdd(&g_mask[(b * HGT + y) * WID + x], mv[i]);
    }
}

// ---------------------------------------------------------------------------
// Kernel 3: fused per-tap GEMM (128 points x 64 out, K=64) + vector-red
// scatter. 256 threads = 16x16; thread (ty,tx) owns 8 m-rows x 4 channels.
// Proven R8 shape: m-pair packed A (k-major smem), 4 B splats, 16 FFMA2/k,
// 4 CTAs/SM (reg cap 64), mainloop unroll 8.
// ---------------------------------------------------------------------------
__global__ __launch_bounds__(256, 4) void conv_scatter_kernel(
    const float* __restrict__ values, const float* __restrict__ kern,
    const void* __restrict__ idx, float* __restrict__ dense) {
    __shared__ float As[64][132];   // k-major values tile (+4 pad), ~33 KB
    __shared__ float Bs[64][64];    // one tap's 64x64 kernel slice, 16 KB
    __shared__ int Pb[128], Py[128], Px[128];

    const int tid = threadIdx.x;
    const int m0 = blockIdx.x * 128;
    const int mode = g_mode[0];

    // Point coords first so their LDGs overlap the A staging below.
    for (int i = tid; i < 128; i += 256) {
        int b, y, x;
        load_row3(idx, m0 + i, mode, b, y, x);
        Pb[i] = b; Py[i] = y; Px[i] = x;
    }
    // Stage A transposed: coalesced float4 gmem reads, scalar smem stores.
    for (int i = tid; i < 128 * 16; i += 256) {
        int m = i >> 4;
        int c = (i & 15) << 2;
        float4 v = *reinterpret_cast<const float4*>(values + (size_t)(m0 + m) * NCH + c);
        As[c + 0][m] = v.x;
        As[c + 1][m] = v.y;
        As[c + 2][m] = v.z;
        As[c + 3][m] = v.w;
    }

    const int ty = tid >> 4;   // 0..15 -> 8 consecutive m-rows each
    const int tx = tid & 15;   // 0..15 -> 4 channels each

#pragma unroll 1
    for (int tap = 0; tap < 9; ++tap) {
        __syncthreads();
        const float4* bsrc = reinterpret_cast<const float4*>(kern + (size_t)tap * NCH * NCH);
        for (int i = tid; i < 64 * 16; i += 256)
            reinterpret_cast<float4*>(Bs)[i] = bsrc[i];
        __syncthreads();

        unsigned long long acc[4][4];   // [m-pair][channel]
#pragma unroll
        for (int mp = 0; mp < 4; ++mp)
#pragma unroll
            for (int n = 0; n < 4; ++n) acc[mp][n] = 0ull;

#pragma unroll 8
        for (int k = 0; k < 64; ++k) {
            // A: 8 consecutive m values as 4 pre-packed f32x2 pairs.
            ulonglong2 A0 = *reinterpret_cast<const ulonglong2*>(&As[k][ty * 8]);
            ulonglong2 A1 = *reinterpret_cast<const ulonglong2*>(&As[k][ty * 8 + 4]);
            // B: one LDS.128, then 4 channel splats.
            float4 b = *reinterpret_cast<const float4*>(&Bs[k][tx * 4]);
            unsigned long long sb0 = splat2(b.x), sb1 = splat2(b.y);
            unsigned long long sb2 = splat2(b.z), sb3 = splat2(b.w);
            acc[0][0] = fma2(A0.x, sb0, acc[0][0]);
            acc[0][1] = fma2(A0.x, sb1, acc[0][1]);
            acc[0][2] = fma2(A0.x, sb2, acc[0][2]);
            acc[0][3] = fma2(A0.x, sb3, acc[0][3]);
            acc[1][0] = fma2(A0.y, sb0, acc[1][0]);
            acc[1][1] = fma2(A0.y, sb1, acc[1][1]);
            acc[1][2] = fma2(A0.y, sb2, acc[1][2]);
            acc[1][3] = fma2(A0.y, sb3, acc[1][3]);
            acc[2][0] = fma2(A1.x, sb0, acc[2][0]);
            acc[2][1] = fma2(A1.x, sb1, acc[2][1]);
            acc[2][2] = fma2(A1.x, sb2, acc[2][2]);
            acc[2][3] = fma2(A1.x, sb3, acc[2][3]);
            acc[3][0] = fma2(A1.y, sb0, acc[3][0]);
            acc[3][1] = fma2(A1.y, sb1, acc[3][1]);
            acc[3][2] = fma2(A1.y, sb2, acc[3][2]);
            acc[3][3] = fma2(A1.y, sb3, acc[3][3]);
        }

        const int dy = tap / 3 - 1;
        const int dx = tap % 3 - 1;
#pragma unroll
        for (int mp = 0; mp < 4; ++mp) {
#pragma unroll
            for (int e = 0; e < 2; ++e) {
                int m = ty * 8 + mp * 2 + e;
                int sy = Py[m] + dy;
                sy = sy < 0 ? 0 : (sy > HGT - 1 ? HGT - 1 : sy);
                int sx = Px[m] + dx;
                sx = sx < 0 ? 0 : (sx > WID - 1 ? WID - 1 : sx);
                float* p = dense + ((((size_t)Pb[m] * HGT + sy) * WID + sx) * NCH) + tx * 4;
                float f0, f1, f2, f3;
                if (e == 0) {
                    f0 = __uint_as_float((unsigned int)acc[mp][0]);
                    f1 = __uint_as_float((unsigned int)acc[mp][1]);
                    f2 = __uint_as_float((unsigned int)acc[mp][2]);
                    f3 = __uint_as_float((unsigned int)acc[mp][3]);
                } else {
                    f0 = __uint_as_float((unsigned int)(acc[mp][0] >> 32));
                    f1 = __uint_as_float((unsigned int)(acc[mp][1] >> 32));
                    f2 = __uint_as_float((unsigned int)(acc[mp][2] >> 32));
                    f3 = __uint_as_float((unsigned int)(acc[mp][3] >> 32));
                }
                asm volatile("red.global.add.v4.f32 [%0], {%1, %2, %3, %4};"
                             :: "l"(p), "f"(f0), "f"(f1), "f"(f2), "f"(f3)
                             : "memory");
            }
        }
    }
}

// ---------------------------------------------------------------------------
// Kernel 4: epilogue  out = (dense + mask*bias) * mask   (in place on d_out)
// One thread handles 4 consecutive float4s (a quarter pixel): mask loaded
// once, 4 independent load/store chains for MLP; m==0 (~78% of pixels)
// skips the dense reads entirely and stores zeros.
// ---------------------------------------------------------------------------
__global__ void epilogue_kernel(float4* __restrict__ out4,
                                const float4* __restrict__ bias4) {
    int t = blockIdx.x * blockDim.x + threadIdx.x;   // quarter-pixel index
    int base = t * 4;                                // first float4 of quarter
    float m = g_mask[t >> 2];
    if (m == 0.f) {
        float4 z = make_float4(0.f, 0.f, 0.f, 0.f);
#pragma unroll
        for (int j = 0; j < 4; ++j) out4[base + j] = z;
        return;
    }
    int q = (t & 3) * 4;                             // bias quarter offset
#pragma unroll
    for (int j = 0; j < 4; ++j) {
        float4 d = out4[base + j];
        float4 bv = __ldg(&bias4[q + j]);
        d.x = (d.x + m * bv.x) * m;
        d.y = (d.y + m * bv.y) * m;
        d.z = (d.z + m * bv.z) * m;
        d.w = (d.w + m * bv.w) * m;
        out4[base + j] = d;
    }
}

// ---------------------------------------------------------------------------
extern "C" void kernel_launch(void* const* d_in, const int* in_sizes, int n_in,
                              void* d_out, int out_size) {
    const float* values = nullptr;
    const float* kern = nullptr;
    const float* bias = nullptr;
    const float* mask_values = nullptr;
    const void* indices = nullptr;
    const void* mask_indices = nullptr;

    for (int i = 0; i < n_in; ++i) {
        int s = in_sizes[i];
        if (s == 8388608)      values = (const float*)d_in[i];
        else if (s == 36864)   kern = (const float*)d_in[i];
        else if (s == 64)      bias = (const float*)d_in[i];
        else if (s == 131072)  mask_values = (const float*)d_in[i];
        else if (s == 393216 || s == 786432) {
            if (!indices) indices = d_in[i];
            else          mask_indices = d_in[i];
        }
    }
    if (!values)       values       = (const float*)d_in[0];
    if (!kern)         kern         = (const float*)d_in[1];
    if (!bias)         bias         = (const float*)d_in[2];
    if (!mask_values)  mask_values  = (const float*)d_in[3];
    if (!indices)      indices      = d_in[4];
    if (!mask_indices) mask_indices = d_in[5];

    float* out = (float*)d_out;
    const int n_out4 = NB * HGT * WID * NCH / 4;  // 8388608

    zero_kernel<<<(n_out4 + 255) / 256, 256>>>((float4*)out, n_out4,
                                               indices, mask_indices);
    mask_scatter_kernel<<<(NMASK + 255) / 256, 256>>>(mask_indices, mask_values);
    conv_scatter_kernel<<<NPTS / 128, 256>>>(values, kern, indices, out);
    epilogue_kernel<<<n_out4 / 4 / 256, 256>>>((float4*)out, (const float4*)bias);
}